// round 10
// baseline (speedup 1.0000x reference)
#include <cuda_runtime.h>
#include <cuda_fp16.h>

#define NN 100000
#define NE 1600000
#define HID 64
#define NEG_SLOPE 0.2f
#define CAP 64              // slots per node; deg~Poisson(16), P(>=64) ~ 1e-19

// ---------------- scratch (device globals) ----------------
__device__ __half g_h[NN * HID];    // layer-1 pre-attention features (fp16, gather-only)
__device__ float  g_hl[NN * HID];   // layer-1 output (GEMM2 input, fp32)
__device__ __half g_h2[NN * HID];   // layer-2 pre-attention features (fp16)
__device__ float  g_as[NN];
__device__ float  g_ad[NN];
__device__ float  g_as2[NN];
__device__ float  g_ad2[NN];
__device__ int    g_cnt[NN];
__device__ int    g_slots[(size_t)NN * CAP];

// ---------------- f32x2 helpers ----------------
__device__ __forceinline__ unsigned long long ffma2(unsigned long long a,
                                                    unsigned long long b,
                                                    unsigned long long c) {
    unsigned long long d;
    asm("fma.rn.f32x2 %0,%1,%2,%3;" : "=l"(d) : "l"(a), "l"(b), "l"(c));
    return d;
}
__device__ __forceinline__ unsigned long long dup2(float x) {
    unsigned long long r;
    asm("mov.b64 %0,{%1,%1};" : "=l"(r) : "f"(x));
    return r;
}
__device__ __forceinline__ float2 unpk(unsigned long long p) {
    float2 r;
    asm("mov.b64 {%0,%1},%2;" : "=f"(r.x), "=f"(r.y) : "l"(p));
    return r;
}
__device__ __forceinline__ float lrelu(float v) {
    return (v > 0.0f) ? v : NEG_SLOPE * v;
}

// ================= adjacency build (slot-based, no scan) =================
__global__ void zero_kernel() {
    int i = blockIdx.x * blockDim.x + threadIdx.x;
    if (i < NN) g_cnt[i] = 0;
}
__global__ void fill_kernel(const int* __restrict__ ei) {
    int e = blockIdx.x * blockDim.x + threadIdx.x;
    if (e >= NE) return;
    int s = ei[e], d = ei[NE + e];
    int idx = atomicAdd(&g_cnt[d], 1);
    if (idx < CAP) g_slots[(size_t)d * CAP + idx] = s;
}

// ============ tiled GEMM (128x64, FFMA2) + fused scores; fp16 H output ============
template<int K>
__global__ void __launch_bounds__(256) gemm_kernel(const float* __restrict__ X,
                                                   const float* __restrict__ W,
                                                   const float* __restrict__ a_s,
                                                   const float* __restrict__ a_d,
                                                   __half* __restrict__ H,
                                                   float* __restrict__ as_out,
                                                   float* __restrict__ ad_out) {
    __shared__ float xs[16][132];
    __shared__ float ws[16][64];
    int t = threadIdx.x;
    int rowblk = blockIdx.x * 128;

    int col4 = (t & 15) * 4;
    int r0   = (t >> 4) * 8;

    unsigned long long acc[4][4];
    #pragma unroll
    for (int i = 0; i < 4; i++)
        #pragma unroll
        for (int j = 0; j < 4; j++) acc[i][j] = 0ull;

    int lrow = t >> 1;
    int lk   = (t & 1) * 8;
    int grow = rowblk + lrow; if (grow >= NN) grow = NN - 1;
    const float4* xsrc = (const float4*)(X + (size_t)grow * K);

    for (int k0 = 0; k0 < K; k0 += 16) {
        float4 v0 = xsrc[(k0 + lk) >> 2];
        float4 v1 = xsrc[(k0 + lk + 4) >> 2];
        float4 wv4 = ((const float4*)(W + k0 * 64))[t];
        __syncthreads();
        xs[lk + 0][lrow] = v0.x; xs[lk + 1][lrow] = v0.y;
        xs[lk + 2][lrow] = v0.z; xs[lk + 3][lrow] = v0.w;
        xs[lk + 4][lrow] = v1.x; xs[lk + 5][lrow] = v1.y;
        xs[lk + 6][lrow] = v1.z; xs[lk + 7][lrow] = v1.w;
        ((float4*)ws)[t] = wv4;
        __syncthreads();
        #pragma unroll
        for (int kk = 0; kk < 16; kk++) {
            float4 wv = *(const float4*)&ws[kk][col4];
            unsigned long long wd0 = dup2(wv.x), wd1 = dup2(wv.y),
                               wd2 = dup2(wv.z), wd3 = dup2(wv.w);
            #pragma unroll
            for (int i = 0; i < 4; i++) {
                unsigned long long xp =
                    *(const unsigned long long*)&xs[kk][r0 + 2 * i];
                acc[i][0] = ffma2(xp, wd0, acc[i][0]);
                acc[i][1] = ffma2(xp, wd1, acc[i][1]);
                acc[i][2] = ffma2(xp, wd2, acc[i][2]);
                acc[i][3] = ffma2(xp, wd3, acc[i][3]);
            }
        }
    }

    int orow = rowblk + r0;
    float2 c[4][4];
    #pragma unroll
    for (int i = 0; i < 4; i++) {
        #pragma unroll
        for (int j = 0; j < 4; j++) c[i][j] = unpk(acc[i][j]);
        int rlo = orow + 2 * i, rhi = rlo + 1;
        if (rlo < NN) {
            union { __half2 h[2]; uint2 u; } pk;
            pk.h[0] = __floats2half2_rn(c[i][0].x, c[i][1].x);
            pk.h[1] = __floats2half2_rn(c[i][2].x, c[i][3].x);
            *(uint2*)(H + (size_t)rlo * 64 + col4) = pk.u;
        }
        if (rhi < NN) {
            union { __half2 h[2]; uint2 u; } pk;
            pk.h[0] = __floats2half2_rn(c[i][0].y, c[i][1].y);
            pk.h[1] = __floats2half2_rn(c[i][2].y, c[i][3].y);
            *(uint2*)(H + (size_t)rhi * 64 + col4) = pk.u;
        }
    }

    float4 asv = *(const float4*)(a_s + col4);
    float4 adv = *(const float4*)(a_d + col4);
    float ps[8], pd[8];
    #pragma unroll
    for (int i = 0; i < 4; i++) {
        ps[2*i]   = c[i][0].x*asv.x + c[i][1].x*asv.y + c[i][2].x*asv.z + c[i][3].x*asv.w;
        ps[2*i+1] = c[i][0].y*asv.x + c[i][1].y*asv.y + c[i][2].y*asv.z + c[i][3].y*asv.w;
        pd[2*i]   = c[i][0].x*adv.x + c[i][1].x*adv.y + c[i][2].x*adv.z + c[i][3].x*adv.w;
        pd[2*i+1] = c[i][0].y*adv.x + c[i][1].y*adv.y + c[i][2].y*adv.z + c[i][3].y*adv.w;
    }
    #pragma unroll
    for (int r = 0; r < 8; r++) {
        #pragma unroll
        for (int o = 8; o; o >>= 1) {
            ps[r] += __shfl_down_sync(0xffffffffu, ps[r], o, 16);
            pd[r] += __shfl_down_sync(0xffffffffu, pd[r], o, 16);
        }
    }
    if ((t & 15) == 0) {
        #pragma unroll
        for (int r = 0; r < 8; r++) {
            int row = orow + r;
            if (row < NN) { as_out[row] = ps[r]; ad_out[row] = pd[r]; }
        }
    }
}

// ---- accumulate 8 halves (one uint4) scaled by w into acc[8] ----
__device__ __forceinline__ void accum8(float* acc, uint4 raw, float w) {
    float2 p0 = __half22float2(*(const __half2*)&raw.x);
    float2 p1 = __half22float2(*(const __half2*)&raw.y);
    float2 p2 = __half22float2(*(const __half2*)&raw.z);
    float2 p3 = __half22float2(*(const __half2*)&raw.w);
    acc[0] = fmaf(w, p0.x, acc[0]); acc[1] = fmaf(w, p0.y, acc[1]);
    acc[2] = fmaf(w, p1.x, acc[2]); acc[3] = fmaf(w, p1.y, acc[3]);
    acc[4] = fmaf(w, p2.x, acc[4]); acc[5] = fmaf(w, p2.y, acc[5]);
    acc[6] = fmaf(w, p3.x, acc[6]); acc[7] = fmaf(w, p3.y, acc[7]);
}

// -------- cooperative gather, 4 edges concurrent (8 lanes x 8 cols each) --------
// After return: acc[0..8) = softmax-weighted sums for cols [l8*8, l8*8+8),
// valid on ALL lanes (duplicated across the 4 groups); inv = 1/den.
__device__ __forceinline__ void gather8(const __half* __restrict__ h,
                                        const float* __restrict__ as,
                                        const float* __restrict__ ad,
                                        int n, int lane,
                                        float* acc, float& inv) {
    int deg = g_cnt[n];
    if (deg > CAP) deg = CAP;
    const int* slots = g_slots + (size_t)n * CAP;
    float adn = ad[n];

    // lane-parallel weights, each edge once
    int   sA = n, sB = n;
    float wA = 0.0f, wB = 0.0f;
    if (lane < deg) {
        sA = slots[lane];
        float e = as[sA] + adn;
        wA = __expf((e > 0.0f) ? e : NEG_SLOPE * e);
    }
    if (lane + 32 < deg) {
        sB = slots[lane + 32];
        float e = as[sB] + adn;
        wB = __expf((e > 0.0f) ? e : NEG_SLOPE * e);
    }
    float es = as[n] + adn;
    float wself = __expf((es > 0.0f) ? es : NEG_SLOPE * es);

    float den = wA + wB;
    #pragma unroll
    for (int o = 16; o; o >>= 1)
        den += __shfl_xor_sync(0xffffffffu, den, o);
    den += wself;

    int q  = lane >> 3;          // edge-group 0..3
    int l8 = lane & 7;           // 8 cols per lane
    const __half* hb = h + l8 * 8;

    #pragma unroll
    for (int i = 0; i < 8; i++) acc[i] = 0.0f;

    // self edge: group 0 only
    if (q == 0) {
        uint4 raw = *(const uint4*)(hb + (size_t)n * HID);
        accum8(acc, raw, wself);
    }

    int m1 = (deg < 32) ? deg : 32;
    int ng1 = (m1 + 3) >> 2;
    for (int g = 0; g < ng1; g++) {
        int e = 4 * g + q;
        int   src = __shfl_sync(0xffffffffu, sA, e & 31);
        float w   = __shfl_sync(0xffffffffu, wA, e & 31);
        if (e >= m1) { w = 0.0f; src = n; }
        uint4 raw = *(const uint4*)(hb + (size_t)src * HID);
        accum8(acc, raw, w);
    }
    int m2 = deg - 32;
    int ng2 = (m2 > 0) ? ((m2 + 3) >> 2) : 0;
    for (int g = 0; g < ng2; g++) {
        int e = 4 * g + q;
        int   src = __shfl_sync(0xffffffffu, sB, e & 31);
        float w   = __shfl_sync(0xffffffffu, wB, e & 31);
        if (e >= m2) { w = 0.0f; src = n; }
        uint4 raw = *(const uint4*)(hb + (size_t)src * HID);
        accum8(acc, raw, w);
    }

    // combine the 4 edge-groups (lanes owning same cols: xor bits 3,4)
    #pragma unroll
    for (int i = 0; i < 8; i++) {
        acc[i] += __shfl_xor_sync(0xffffffffu, acc[i], 8);
        acc[i] += __shfl_xor_sync(0xffffffffu, acc[i], 16);
    }
    inv = 1.0f / den;
}

// ============ aggregate layer1 + bias + relu -> g_hl (fp32) ============
__global__ void __launch_bounds__(256) agg1_kernel(const __half* __restrict__ h,
                                                   const float* __restrict__ b1,
                                                   float* __restrict__ HL) {
    int n = (blockIdx.x * blockDim.x + threadIdx.x) >> 5;
    int lane = threadIdx.x & 31;
    if (n >= NN) return;

    float acc[8], inv;
    gather8(h, g_as, g_ad, n, lane, acc, inv);

    if ((lane >> 3) == 0) {     // group 0 stores (results duplicated across groups)
        int l8 = lane & 7;
        const float4* b4 = (const float4*)(b1 + l8 * 8);
        float4 bl = b4[0], bh = b4[1];
        float v0 = fmaf(acc[0], inv, bl.x); v0 = v0 > 0.f ? v0 : 0.f;
        float v1 = fmaf(acc[1], inv, bl.y); v1 = v1 > 0.f ? v1 : 0.f;
        float v2 = fmaf(acc[2], inv, bl.z); v2 = v2 > 0.f ? v2 : 0.f;
        float v3 = fmaf(acc[3], inv, bl.w); v3 = v3 > 0.f ? v3 : 0.f;
        float v4 = fmaf(acc[4], inv, bh.x); v4 = v4 > 0.f ? v4 : 0.f;
        float v5 = fmaf(acc[5], inv, bh.y); v5 = v5 > 0.f ? v5 : 0.f;
        float v6 = fmaf(acc[6], inv, bh.z); v6 = v6 > 0.f ? v6 : 0.f;
        float v7 = fmaf(acc[7], inv, bh.w); v7 = v7 > 0.f ? v7 : 0.f;
        float4* o4 = (float4*)(HL + (size_t)n * HID + l8 * 8);
        o4[0] = make_float4(v0, v1, v2, v3);
        o4[1] = make_float4(v4, v5, v6, v7);
    }
}

// ============ final: aggregate layer2 + bias + relu + both heads ============
__global__ void __launch_bounds__(256) agg2_heads_kernel(const __half* __restrict__ h,
                                                         const float* __restrict__ b2,
                                                         const float* __restrict__ Wf,
                                                         const float* __restrict__ bf,
                                                         const float* __restrict__ Ws,
                                                         const float* __restrict__ bs,
                                                         float* __restrict__ out) {
    int n = (blockIdx.x * blockDim.x + threadIdx.x) >> 5;
    int lane = threadIdx.x & 31;
    if (n >= NN) return;

    float acc[8], inv;
    gather8(h, g_as2, g_ad2, n, lane, acc, inv);

    int q = lane >> 3, l8 = lane & 7;
    float v[8];
    if (q == 0) {
        const float4* b4 = (const float4*)(b2 + l8 * 8);
        float4 bl = b4[0], bh = b4[1];
        v[0] = fmaf(acc[0], inv, bl.x);
        v[1] = fmaf(acc[1], inv, bl.y);
        v[2] = fmaf(acc[2], inv, bl.z);
        v[3] = fmaf(acc[3], inv, bl.w);
        v[4] = fmaf(acc[4], inv, bh.x);
        v[5] = fmaf(acc[5], inv, bh.y);
        v[6] = fmaf(acc[6], inv, bh.z);
        v[7] = fmaf(acc[7], inv, bh.w);
        #pragma unroll
        for (int i = 0; i < 8; i++) v[i] = v[i] > 0.0f ? v[i] : 0.0f;
    } else {
        #pragma unroll
        for (int i = 0; i < 8; i++) v[i] = 0.0f;   // duplicates contribute zero
    }

    float hacc[10];
    #pragma unroll
    for (int j = 0; j < 3; j++) {
        float s = 0.0f;
        #pragma unroll
        for (int i = 0; i < 8; i++)
            s = fmaf(v[i], Wf[(l8 * 8 + i) * 3 + j], s);
        hacc[j] = s;
    }
    #pragma unroll
    for (int j = 0; j < 7; j++) {
        float s = 0.0f;
        #pragma unroll
        for (int i = 0; i < 8; i++)
            s = fmaf(v[i], Ws[(l8 * 8 + i) * 7 + j], s);
        hacc[3 + j] = s;
    }
    #pragma unroll
    for (int j = 0; j < 10; j++) {
        #pragma unroll
        for (int o = 16; o; o >>= 1)
            hacc[j] += __shfl_down_sync(0xffffffffu, hacc[j], o);
    }
    if (lane == 0) {
        #pragma unroll
        for (int j = 0; j < 3; j++) out[(size_t)n * 3 + j] = hacc[j] + bf[j];
        #pragma unroll
        for (int j = 0; j < 7; j++)
            out[(size_t)NN * 3 + (size_t)n * 7 + j] = hacc[3 + j] + bs[j];
    }
}

extern "C" void kernel_launch(void* const* d_in, const int* in_sizes, int n_in,
                              void* d_out, int out_size) {
    const float* x    = (const float*)d_in[0];
    const int*   ei   = (const int*)d_in[1];
    const float* W1   = (const float*)d_in[2];
    const float* as1  = (const float*)d_in[3];
    const float* ad1  = (const float*)d_in[4];
    const float* b1   = (const float*)d_in[5];
    const float* W2   = (const float*)d_in[6];
    const float* as2  = (const float*)d_in[7];
    const float* ad2  = (const float*)d_in[8];
    const float* b2   = (const float*)d_in[9];
    const float* Wf   = (const float*)d_in[10];
    const float* bf   = (const float*)d_in[11];
    const float* Ws   = (const float*)d_in[12];
    const float* bs   = (const float*)d_in[13];
    float* out = (float*)d_out;

    __half* d_gh;   cudaGetSymbolAddress((void**)&d_gh,   g_h);
    float*  d_ghl;  cudaGetSymbolAddress((void**)&d_ghl,  g_hl);
    __half* d_gh2;  cudaGetSymbolAddress((void**)&d_gh2,  g_h2);
    float*  d_gas;  cudaGetSymbolAddress((void**)&d_gas,  g_as);
    float*  d_gad;  cudaGetSymbolAddress((void**)&d_gad,  g_ad);
    float*  d_gas2; cudaGetSymbolAddress((void**)&d_gas2, g_as2);
    float*  d_gad2; cudaGetSymbolAddress((void**)&d_gad2, g_ad2);

    const int TB = 256;
    dim3 gNode((NN + TB - 1) / TB);
    dim3 gEdge((NE + TB - 1) / TB);
    dim3 gGemm((NN + 127) / 128);
    dim3 gWarpNode(((size_t)NN * 32 + TB - 1) / TB);

    // ---- adjacency build ----
    zero_kernel<<<gNode, TB>>>();                                  // launch 0
    fill_kernel<<<gEdge, TB>>>(ei);                                // launch 1

    // ---- layer 1 ----
    gemm_kernel<256><<<gGemm, TB>>>(x, W1, as1, ad1, d_gh, d_gas, d_gad);  // launch 2
    agg1_kernel<<<gWarpNode, TB>>>(d_gh, b1, d_ghl);               // launch 3 (profiled)

    // ---- layer 2 ----
    gemm_kernel<64><<<gGemm, TB>>>(d_ghl, W2, as2, ad2, d_gh2, d_gas2, d_gad2);
    agg2_heads_kernel<<<gWarpNode, TB>>>(d_gh2, b2, Wf, bf, Ws, bs, out);
}

// round 11
// speedup vs baseline: 1.1460x; 1.1460x over previous
#include <cuda_runtime.h>
#include <cuda_fp16.h>

#define NN 100000
#define NE 1600000
#define HID 64
#define NEG_SLOPE 0.2f
#define CAP 64              // slots per node; deg~Poisson(16), P(>=64) ~ 1e-19

// ---------------- scratch (device globals) ----------------
__device__ float g_h[NN * HID];     // layer-1 pre-attention features (fp32)
__device__ float g_hl[NN * HID];    // layer-1 output (GEMM2 input)
__device__ float g_h2[NN * HID];    // layer-2 pre-attention features
__device__ float g_as[NN];
__device__ float g_ad[NN];
__device__ float g_as2[NN];
__device__ float g_ad2[NN];
__device__ int   g_cnt[NN];
__device__ int   g_slots[(size_t)NN * CAP];

// ---------------- f32x2 helpers ----------------
__device__ __forceinline__ unsigned long long ffma2(unsigned long long a,
                                                    unsigned long long b,
                                                    unsigned long long c) {
    unsigned long long d;
    asm("fma.rn.f32x2 %0,%1,%2,%3;" : "=l"(d) : "l"(a), "l"(b), "l"(c));
    return d;
}
__device__ __forceinline__ unsigned long long dup2(float x) {
    unsigned long long r;
    asm("mov.b64 %0,{%1,%1};" : "=l"(r) : "f"(x));
    return r;
}
__device__ __forceinline__ float2 unpk(unsigned long long p) {
    float2 r;
    asm("mov.b64 {%0,%1},%2;" : "=f"(r.x), "=f"(r.y) : "l"(p));
    return r;
}

// ================= adjacency build (slot-based, no scan) =================
__global__ void zero_kernel() {
    int i = blockIdx.x * blockDim.x + threadIdx.x;
    if (i < NN) g_cnt[i] = 0;
}
__global__ void fill_kernel(const int* __restrict__ ei) {
    int e = blockIdx.x * blockDim.x + threadIdx.x;
    if (e >= NE) return;
    int s = ei[e], d = ei[NE + e];
    int idx = atomicAdd(&g_cnt[d], 1);
    if (idx < CAP) g_slots[(size_t)d * CAP + idx] = s;
}

// ============ tiled GEMM (128x64, FFMA2) + fused scores ============
template<int K>
__global__ void __launch_bounds__(256) gemm_kernel(const float* __restrict__ X,
                                                   const float* __restrict__ W,
                                                   const float* __restrict__ a_s,
                                                   const float* __restrict__ a_d,
                                                   float* __restrict__ H,
                                                   float* __restrict__ as_out,
                                                   float* __restrict__ ad_out) {
    __shared__ float xs[16][132];
    __shared__ float ws[16][64];
    int t = threadIdx.x;
    int rowblk = blockIdx.x * 128;

    int col4 = (t & 15) * 4;
    int r0   = (t >> 4) * 8;

    unsigned long long acc[4][4];
    #pragma unroll
    for (int i = 0; i < 4; i++)
        #pragma unroll
        for (int j = 0; j < 4; j++) acc[i][j] = 0ull;

    int lrow = t >> 1;
    int lk   = (t & 1) * 8;
    int grow = rowblk + lrow; if (grow >= NN) grow = NN - 1;
    const float4* xsrc = (const float4*)(X + (size_t)grow * K);

    for (int k0 = 0; k0 < K; k0 += 16) {
        float4 v0 = xsrc[(k0 + lk) >> 2];
        float4 v1 = xsrc[(k0 + lk + 4) >> 2];
        float4 wv4 = ((const float4*)(W + k0 * 64))[t];
        __syncthreads();
        xs[lk + 0][lrow] = v0.x; xs[lk + 1][lrow] = v0.y;
        xs[lk + 2][lrow] = v0.z; xs[lk + 3][lrow] = v0.w;
        xs[lk + 4][lrow] = v1.x; xs[lk + 5][lrow] = v1.y;
        xs[lk + 6][lrow] = v1.z; xs[lk + 7][lrow] = v1.w;
        ((float4*)ws)[t] = wv4;
        __syncthreads();
        #pragma unroll
        for (int kk = 0; kk < 16; kk++) {
            float4 wv = *(const float4*)&ws[kk][col4];
            unsigned long long wd0 = dup2(wv.x), wd1 = dup2(wv.y),
                               wd2 = dup2(wv.z), wd3 = dup2(wv.w);
            #pragma unroll
            for (int i = 0; i < 4; i++) {
                unsigned long long xp =
                    *(const unsigned long long*)&xs[kk][r0 + 2 * i];
                acc[i][0] = ffma2(xp, wd0, acc[i][0]);
                acc[i][1] = ffma2(xp, wd1, acc[i][1]);
                acc[i][2] = ffma2(xp, wd2, acc[i][2]);
                acc[i][3] = ffma2(xp, wd3, acc[i][3]);
            }
        }
    }

    int orow = rowblk + r0;
    float2 c[4][4];
    #pragma unroll
    for (int i = 0; i < 4; i++) {
        #pragma unroll
        for (int j = 0; j < 4; j++) c[i][j] = unpk(acc[i][j]);
        int rlo = orow + 2 * i, rhi = rlo + 1;
        if (rlo < NN)
            *(float4*)(H + (size_t)rlo * 64 + col4) =
                make_float4(c[i][0].x, c[i][1].x, c[i][2].x, c[i][3].x);
        if (rhi < NN)
            *(float4*)(H + (size_t)rhi * 64 + col4) =
                make_float4(c[i][0].y, c[i][1].y, c[i][2].y, c[i][3].y);
    }

    float4 asv = *(const float4*)(a_s + col4);
    float4 adv = *(const float4*)(a_d + col4);
    float ps[8], pd[8];
    #pragma unroll
    for (int i = 0; i < 4; i++) {
        ps[2*i]   = c[i][0].x*asv.x + c[i][1].x*asv.y + c[i][2].x*asv.z + c[i][3].x*asv.w;
        ps[2*i+1] = c[i][0].y*asv.x + c[i][1].y*asv.y + c[i][2].y*asv.z + c[i][3].y*asv.w;
        pd[2*i]   = c[i][0].x*adv.x + c[i][1].x*adv.y + c[i][2].x*adv.z + c[i][3].x*adv.w;
        pd[2*i+1] = c[i][0].y*adv.x + c[i][1].y*adv.y + c[i][2].y*adv.z + c[i][3].y*adv.w;
    }
    #pragma unroll
    for (int r = 0; r < 8; r++) {
        #pragma unroll
        for (int o = 8; o; o >>= 1) {
            ps[r] += __shfl_down_sync(0xffffffffu, ps[r], o, 16);
            pd[r] += __shfl_down_sync(0xffffffffu, pd[r], o, 16);
        }
    }
    if ((t & 15) == 0) {
        #pragma unroll
        for (int r = 0; r < 8; r++) {
            int row = orow + r;
            if (row < NN) { as_out[row] = ps[r]; ad_out[row] = pd[r]; }
        }
    }
}

// -------- cooperative softmax-weighted gather (fp32 features) --------
// Lane j computes weight of edge j once; den via warp reduction; accumulation
// broadcasts (s, w) via shuffles, lanes own 2 feature columns (float2 loads).
__device__ __forceinline__ void gather_node(const float* __restrict__ h,
                                            const float* __restrict__ as,
                                            const float* __restrict__ ad,
                                            int n, int lane,
                                            float& h0, float& h1) {
    int deg = g_cnt[n];
    if (deg > CAP) deg = CAP;
    const int* slots = g_slots + (size_t)n * CAP;
    int c0 = 2 * lane;
    float adn = ad[n];

    int   sA = 0, sB = 0;
    float wA = 0.0f, wB = 0.0f;
    if (lane < deg) {
        sA = slots[lane];
        float e = as[sA] + adn;
        wA = __expf((e > 0.0f) ? e : NEG_SLOPE * e);
    }
    if (lane + 32 < deg) {
        sB = slots[lane + 32];
        float e = as[sB] + adn;
        wB = __expf((e > 0.0f) ? e : NEG_SLOPE * e);
    }
    float es = as[n] + adn;
    float wself = __expf((es > 0.0f) ? es : NEG_SLOPE * es);

    float den = wA + wB;
    #pragma unroll
    for (int o = 16; o; o >>= 1)
        den += __shfl_xor_sync(0xffffffffu, den, o);
    den += wself;

    float2 hv = *(const float2*)(h + (size_t)n * HID + c0);
    float accx = wself * hv.x, accy = wself * hv.y;

    int m1 = (deg < 32) ? deg : 32;
    int j = 0;
    for (; j + 4 <= m1; j += 4) {
        int t0 = __shfl_sync(0xffffffffu, sA, j);
        int t1 = __shfl_sync(0xffffffffu, sA, j + 1);
        int t2 = __shfl_sync(0xffffffffu, sA, j + 2);
        int t3 = __shfl_sync(0xffffffffu, sA, j + 3);
        float2 v0 = *(const float2*)(h + (size_t)t0 * HID + c0);
        float2 v1 = *(const float2*)(h + (size_t)t1 * HID + c0);
        float2 v2 = *(const float2*)(h + (size_t)t2 * HID + c0);
        float2 v3 = *(const float2*)(h + (size_t)t3 * HID + c0);
        float w0 = __shfl_sync(0xffffffffu, wA, j);
        float w1 = __shfl_sync(0xffffffffu, wA, j + 1);
        float w2 = __shfl_sync(0xffffffffu, wA, j + 2);
        float w3 = __shfl_sync(0xffffffffu, wA, j + 3);
        accx = fmaf(w0, v0.x, accx); accy = fmaf(w0, v0.y, accy);
        accx = fmaf(w1, v1.x, accx); accy = fmaf(w1, v1.y, accy);
        accx = fmaf(w2, v2.x, accx); accy = fmaf(w2, v2.y, accy);
        accx = fmaf(w3, v3.x, accx); accy = fmaf(w3, v3.y, accy);
    }
    for (; j < m1; j++) {
        int   s = __shfl_sync(0xffffffffu, sA, j);
        float w = __shfl_sync(0xffffffffu, wA, j);
        float2 v = *(const float2*)(h + (size_t)s * HID + c0);
        accx = fmaf(w, v.x, accx); accy = fmaf(w, v.y, accy);
    }
    int m2 = deg - 32;
    j = 0;
    for (; j + 4 <= m2; j += 4) {
        int t0 = __shfl_sync(0xffffffffu, sB, j);
        int t1 = __shfl_sync(0xffffffffu, sB, j + 1);
        int t2 = __shfl_sync(0xffffffffu, sB, j + 2);
        int t3 = __shfl_sync(0xffffffffu, sB, j + 3);
        float2 v0 = *(const float2*)(h + (size_t)t0 * HID + c0);
        float2 v1 = *(const float2*)(h + (size_t)t1 * HID + c0);
        float2 v2 = *(const float2*)(h + (size_t)t2 * HID + c0);
        float2 v3 = *(const float2*)(h + (size_t)t3 * HID + c0);
        float w0 = __shfl_sync(0xffffffffu, wB, j);
        float w1 = __shfl_sync(0xffffffffu, wB, j + 1);
        float w2 = __shfl_sync(0xffffffffu, wB, j + 2);
        float w3 = __shfl_sync(0xffffffffu, wB, j + 3);
        accx = fmaf(w0, v0.x, accx); accy = fmaf(w0, v0.y, accy);
        accx = fmaf(w1, v1.x, accx); accy = fmaf(w1, v1.y, accy);
        accx = fmaf(w2, v2.x, accx); accy = fmaf(w2, v2.y, accy);
        accx = fmaf(w3, v3.x, accx); accy = fmaf(w3, v3.y, accy);
    }
    for (; j < m2; j++) {
        int   s = __shfl_sync(0xffffffffu, sB, j);
        float w = __shfl_sync(0xffffffffu, wB, j);
        float2 v = *(const float2*)(h + (size_t)s * HID + c0);
        accx = fmaf(w, v.x, accx); accy = fmaf(w, v.y, accy);
    }

    float inv = 1.0f / den;
    h0 = accx * inv;
    h1 = accy * inv;
}

// ============ aggregate layer1 + bias + relu -> g_hl ============
__global__ void __launch_bounds__(256) agg1_kernel(const float* __restrict__ h,
                                                   const float* __restrict__ b1,
                                                   float* __restrict__ HL) {
    int n = (blockIdx.x * blockDim.x + threadIdx.x) >> 5;
    int lane = threadIdx.x & 31;
    if (n >= NN) return;
    int c0 = 2 * lane;

    float h0, h1;
    gather_node(h, g_as, g_ad, n, lane, h0, h1);
    h0 += b1[c0]; h1 += b1[c0 + 1];
    h0 = (h0 > 0.0f) ? h0 : 0.0f;
    h1 = (h1 > 0.0f) ? h1 : 0.0f;
    *(float2*)(HL + (size_t)n * HID + c0) = make_float2(h0, h1);
}

// ============ final: aggregate layer2 + bias + relu + both heads ============
__global__ void __launch_bounds__(256) agg2_heads_kernel(const float* __restrict__ h,
                                                         const float* __restrict__ b2,
                                                         const float* __restrict__ Wf,
                                                         const float* __restrict__ bf,
                                                         const float* __restrict__ Ws,
                                                         const float* __restrict__ bs,
                                                         float* __restrict__ out) {
    int n = (blockIdx.x * blockDim.x + threadIdx.x) >> 5;
    int lane = threadIdx.x & 31;
    if (n >= NN) return;
    int c0 = 2 * lane;

    float h0, h1;
    gather_node(h, g_as2, g_ad2, n, lane, h0, h1);
    h0 += b2[c0]; h1 += b2[c0 + 1];
    h0 = (h0 > 0.0f) ? h0 : 0.0f;
    h1 = (h1 > 0.0f) ? h1 : 0.0f;

    float acc[10];
    #pragma unroll
    for (int j = 0; j < 3; j++)
        acc[j] = h0 * Wf[c0 * 3 + j] + h1 * Wf[(c0 + 1) * 3 + j];
    #pragma unroll
    for (int j = 0; j < 7; j++)
        acc[3 + j] = h0 * Ws[c0 * 7 + j] + h1 * Ws[(c0 + 1) * 7 + j];
    #pragma unroll
    for (int j = 0; j < 10; j++) {
        #pragma unroll
        for (int o = 16; o; o >>= 1)
            acc[j] += __shfl_down_sync(0xffffffffu, acc[j], o);
    }
    if (lane == 0) {
        #pragma unroll
        for (int j = 0; j < 3; j++) out[(size_t)n * 3 + j] = acc[j] + bf[j];
        #pragma unroll
        for (int j = 0; j < 7; j++)
            out[(size_t)NN * 3 + (size_t)n * 7 + j] = acc[3 + j] + bs[j];
    }
}

extern "C" void kernel_launch(void* const* d_in, const int* in_sizes, int n_in,
                              void* d_out, int out_size) {
    const float* x    = (const float*)d_in[0];
    const int*   ei   = (const int*)d_in[1];
    const float* W1   = (const float*)d_in[2];
    const float* as1  = (const float*)d_in[3];
    const float* ad1  = (const float*)d_in[4];
    const float* b1   = (const float*)d_in[5];
    const float* W2   = (const float*)d_in[6];
    const float* as2  = (const float*)d_in[7];
    const float* ad2  = (const float*)d_in[8];
    const float* b2   = (const float*)d_in[9];
    const float* Wf   = (const float*)d_in[10];
    const float* bf   = (const float*)d_in[11];
    const float* Ws   = (const float*)d_in[12];
    const float* bs   = (const float*)d_in[13];
    float* out = (float*)d_out;

    float* d_gh;   cudaGetSymbolAddress((void**)&d_gh,   g_h);
    float* d_ghl;  cudaGetSymbolAddress((void**)&d_ghl,  g_hl);
    float* d_gh2;  cudaGetSymbolAddress((void**)&d_gh2,  g_h2);
    float* d_gas;  cudaGetSymbolAddress((void**)&d_gas,  g_as);
    float* d_gad;  cudaGetSymbolAddress((void**)&d_gad,  g_ad);
    float* d_gas2; cudaGetSymbolAddress((void**)&d_gas2, g_as2);
    float* d_gad2; cudaGetSymbolAddress((void**)&d_gad2, g_ad2);

    const int TB = 256;
    dim3 gNode((NN + TB - 1) / TB);
    dim3 gEdge((NE + TB - 1) / TB);
    dim3 gGemm((NN + 127) / 128);
    dim3 gWarpNode(((size_t)NN * 32 + TB - 1) / TB);

    // ---- adjacency build ----
    zero_kernel<<<gNode, TB>>>();                                  // launch 0
    fill_kernel<<<gEdge, TB>>>(ei);                                // launch 1

    // ---- layer 1 ----
    gemm_kernel<256><<<gGemm, TB>>>(x, W1, as1, ad1, d_gh, d_gas, d_gad);  // launch 2
    agg1_kernel<<<gWarpNode, TB>>>(d_gh, b1, d_ghl);               // launch 3 (profiled)

    // ---- layer 2 ----
    gemm_kernel<64><<<gGemm, TB>>>(d_ghl, W2, as2, ad2, d_gh2, d_gas2, d_gad2);
    agg2_heads_kernel<<<gWarpNode, TB>>>(d_gh2, b2, Wf, bf, Ws, bs, out);
}

// round 12
// speedup vs baseline: 1.1638x; 1.0156x over previous
#include <cuda_runtime.h>
#include <cuda_fp16.h>

#define NN 100000
#define NE 1600000
#define HID 64
#define NEG_SLOPE 0.2f
#define CAP 64              // slots per node incl. self; deg~1+Poisson(16), P(>=64) ~ 0

// ---------------- scratch (device globals) ----------------
__device__ __half g_h[NN * HID];    // layer-1 pre-attention features (fp16, gather-only)
__device__ float  g_hl[NN * HID];   // layer-1 output (GEMM2 input, fp32)
__device__ __half g_h2[NN * HID];   // layer-2 pre-attention features (fp16)
__device__ float  g_as[NN];
__device__ float  g_ad[NN];
__device__ float  g_as2[NN];
__device__ float  g_ad2[NN];
__device__ int    g_cnt[NN];
__device__ int    g_slots[(size_t)NN * CAP];

// ---------------- f32x2 helpers ----------------
__device__ __forceinline__ unsigned long long ffma2(unsigned long long a,
                                                    unsigned long long b,
                                                    unsigned long long c) {
    unsigned long long d;
    asm("fma.rn.f32x2 %0,%1,%2,%3;" : "=l"(d) : "l"(a), "l"(b), "l"(c));
    return d;
}
__device__ __forceinline__ unsigned long long dup2(float x) {
    unsigned long long r;
    asm("mov.b64 %0,{%1,%1};" : "=l"(r) : "f"(x));
    return r;
}
__device__ __forceinline__ float2 unpk(unsigned long long p) {
    float2 r;
    asm("mov.b64 {%0,%1},%2;" : "=f"(r.x), "=f"(r.y) : "l"(p));
    return r;
}

// ================= adjacency build (slot-based; self-loop pre-seeded) =================
__global__ void zero_kernel() {
    int i = blockIdx.x * blockDim.x + threadIdx.x;
    if (i < NN) {
        g_cnt[i] = 1;                       // slot 0 = self loop
        g_slots[(size_t)i * CAP] = i;
    }
}
__global__ void fill_kernel(const int* __restrict__ ei) {
    int e = blockIdx.x * blockDim.x + threadIdx.x;
    if (e >= NE) return;
    int s = ei[e], d = ei[NE + e];
    int idx = atomicAdd(&g_cnt[d], 1);
    if (idx < CAP) g_slots[(size_t)d * CAP + idx] = s;
}

// ============ tiled GEMM (128x64, FFMA2) + fused scores; fp16 H output ============
template<int K>
__global__ void __launch_bounds__(256) gemm_kernel(const float* __restrict__ X,
                                                   const float* __restrict__ W,
                                                   const float* __restrict__ a_s,
                                                   const float* __restrict__ a_d,
                                                   __half* __restrict__ H,
                                                   float* __restrict__ as_out,
                                                   float* __restrict__ ad_out) {
    __shared__ float xs[16][132];
    __shared__ float ws[16][64];
    int t = threadIdx.x;
    int rowblk = blockIdx.x * 128;

    int col4 = (t & 15) * 4;
    int r0   = (t >> 4) * 8;

    unsigned long long acc[4][4];
    #pragma unroll
    for (int i = 0; i < 4; i++)
        #pragma unroll
        for (int j = 0; j < 4; j++) acc[i][j] = 0ull;

    int lrow = t >> 1;
    int lk   = (t & 1) * 8;
    int grow = rowblk + lrow; if (grow >= NN) grow = NN - 1;
    const float4* xsrc = (const float4*)(X + (size_t)grow * K);

    for (int k0 = 0; k0 < K; k0 += 16) {
        float4 v0 = xsrc[(k0 + lk) >> 2];
        float4 v1 = xsrc[(k0 + lk + 4) >> 2];
        float4 wv4 = ((const float4*)(W + k0 * 64))[t];
        __syncthreads();
        xs[lk + 0][lrow] = v0.x; xs[lk + 1][lrow] = v0.y;
        xs[lk + 2][lrow] = v0.z; xs[lk + 3][lrow] = v0.w;
        xs[lk + 4][lrow] = v1.x; xs[lk + 5][lrow] = v1.y;
        xs[lk + 6][lrow] = v1.z; xs[lk + 7][lrow] = v1.w;
        ((float4*)ws)[t] = wv4;
        __syncthreads();
        #pragma unroll
        for (int kk = 0; kk < 16; kk++) {
            float4 wv = *(const float4*)&ws[kk][col4];
            unsigned long long wd0 = dup2(wv.x), wd1 = dup2(wv.y),
                               wd2 = dup2(wv.z), wd3 = dup2(wv.w);
            #pragma unroll
            for (int i = 0; i < 4; i++) {
                unsigned long long xp =
                    *(const unsigned long long*)&xs[kk][r0 + 2 * i];
                acc[i][0] = ffma2(xp, wd0, acc[i][0]);
                acc[i][1] = ffma2(xp, wd1, acc[i][1]);
                acc[i][2] = ffma2(xp, wd2, acc[i][2]);
                acc[i][3] = ffma2(xp, wd3, acc[i][3]);
            }
        }
    }

    int orow = rowblk + r0;
    float2 c[4][4];
    #pragma unroll
    for (int i = 0; i < 4; i++) {
        #pragma unroll
        for (int j = 0; j < 4; j++) c[i][j] = unpk(acc[i][j]);
        int rlo = orow + 2 * i, rhi = rlo + 1;
        if (rlo < NN) {
            union { __half2 h[2]; uint2 u; } pk;
            pk.h[0] = __floats2half2_rn(c[i][0].x, c[i][1].x);
            pk.h[1] = __floats2half2_rn(c[i][2].x, c[i][3].x);
            *(uint2*)(H + (size_t)rlo * 64 + col4) = pk.u;
        }
        if (rhi < NN) {
            union { __half2 h[2]; uint2 u; } pk;
            pk.h[0] = __floats2half2_rn(c[i][0].y, c[i][1].y);
            pk.h[1] = __floats2half2_rn(c[i][2].y, c[i][3].y);
            *(uint2*)(H + (size_t)rhi * 64 + col4) = pk.u;
        }
    }

    float4 asv = *(const float4*)(a_s + col4);
    float4 adv = *(const float4*)(a_d + col4);
    float ps[8], pd[8];
    #pragma unroll
    for (int i = 0; i < 4; i++) {
        ps[2*i]   = c[i][0].x*asv.x + c[i][1].x*asv.y + c[i][2].x*asv.z + c[i][3].x*asv.w;
        ps[2*i+1] = c[i][0].y*asv.x + c[i][1].y*asv.y + c[i][2].y*asv.z + c[i][3].y*asv.w;
        pd[2*i]   = c[i][0].x*adv.x + c[i][1].x*adv.y + c[i][2].x*adv.z + c[i][3].x*adv.w;
        pd[2*i+1] = c[i][0].y*adv.x + c[i][1].y*adv.y + c[i][2].y*adv.z + c[i][3].y*adv.w;
    }
    #pragma unroll
    for (int r = 0; r < 8; r++) {
        #pragma unroll
        for (int o = 8; o; o >>= 1) {
            ps[r] += __shfl_down_sync(0xffffffffu, ps[r], o, 16);
            pd[r] += __shfl_down_sync(0xffffffffu, pd[r], o, 16);
        }
    }
    if ((t & 15) == 0) {
        #pragma unroll
        for (int r = 0; r < 8; r++) {
            int row = orow + r;
            if (row < NN) { as_out[row] = ps[r]; ad_out[row] = pd[r]; }
        }
    }
}

// -------- cooperative softmax-weighted gather (fp16 features, self in slot 0) --------
// Lane j computes weight of edge j once; den via warp reduction; accumulation
// broadcasts (s, w) via shuffles with 8 edges in flight (MLP=8).
__device__ __forceinline__ void gather_node(const __half* __restrict__ h,
                                            const float* __restrict__ as,
                                            const float* __restrict__ ad,
                                            int n, int lane,
                                            float& h0, float& h1) {
    int deg = g_cnt[n];
    if (deg > CAP) deg = CAP;
    const int* slots = g_slots + (size_t)n * CAP;
    int c0 = 2 * lane;
    float adn = ad[n];

    int   sA = n, sB = n;
    float wA = 0.0f, wB = 0.0f;
    if (lane < deg) {
        sA = slots[lane];
        float e = as[sA] + adn;
        wA = __expf((e > 0.0f) ? e : NEG_SLOPE * e);
    }
    if (lane + 32 < deg) {
        sB = slots[lane + 32];
        float e = as[sB] + adn;
        wB = __expf((e > 0.0f) ? e : NEG_SLOPE * e);
    }

    float den = wA + wB;
    #pragma unroll
    for (int o = 16; o; o >>= 1)
        den += __shfl_xor_sync(0xffffffffu, den, o);

    float accx = 0.0f, accy = 0.0f;

    int m1 = (deg < 32) ? deg : 32;
    int j = 0;
    for (; j + 8 <= m1; j += 8) {       // 8 edges in flight
        int   t_[8]; float w_[8]; float2 v_[8];
        #pragma unroll
        for (int u = 0; u < 8; u++) {
            t_[u] = __shfl_sync(0xffffffffu, sA, j + u);
            w_[u] = __shfl_sync(0xffffffffu, wA, j + u);
        }
        #pragma unroll
        for (int u = 0; u < 8; u++)
            v_[u] = __half22float2(*(const __half2*)(h + (size_t)t_[u] * HID + c0));
        #pragma unroll
        for (int u = 0; u < 8; u++) {
            accx = fmaf(w_[u], v_[u].x, accx);
            accy = fmaf(w_[u], v_[u].y, accy);
        }
    }
    for (; j + 4 <= m1; j += 4) {
        int   t_[4]; float w_[4]; float2 v_[4];
        #pragma unroll
        for (int u = 0; u < 4; u++) {
            t_[u] = __shfl_sync(0xffffffffu, sA, j + u);
            w_[u] = __shfl_sync(0xffffffffu, wA, j + u);
        }
        #pragma unroll
        for (int u = 0; u < 4; u++)
            v_[u] = __half22float2(*(const __half2*)(h + (size_t)t_[u] * HID + c0));
        #pragma unroll
        for (int u = 0; u < 4; u++) {
            accx = fmaf(w_[u], v_[u].x, accx);
            accy = fmaf(w_[u], v_[u].y, accy);
        }
    }
    for (; j < m1; j++) {
        int   s = __shfl_sync(0xffffffffu, sA, j);
        float w = __shfl_sync(0xffffffffu, wA, j);
        float2 v = __half22float2(*(const __half2*)(h + (size_t)s * HID + c0));
        accx = fmaf(w, v.x, accx); accy = fmaf(w, v.y, accy);
    }

    int m2 = deg - 32;
    j = 0;
    for (; j + 4 <= m2; j += 4) {
        int   t_[4]; float w_[4]; float2 v_[4];
        #pragma unroll
        for (int u = 0; u < 4; u++) {
            t_[u] = __shfl_sync(0xffffffffu, sB, j + u);
            w_[u] = __shfl_sync(0xffffffffu, wB, j + u);
        }
        #pragma unroll
        for (int u = 0; u < 4; u++)
            v_[u] = __half22float2(*(const __half2*)(h + (size_t)t_[u] * HID + c0));
        #pragma unroll
        for (int u = 0; u < 4; u++) {
            accx = fmaf(w_[u], v_[u].x, accx);
            accy = fmaf(w_[u], v_[u].y, accy);
        }
    }
    for (; j < m2; j++) {
        int   s = __shfl_sync(0xffffffffu, sB, j);
        float w = __shfl_sync(0xffffffffu, wB, j);
        float2 v = __half22float2(*(const __half2*)(h + (size_t)s * HID + c0));
        accx = fmaf(w, v.x, accx); accy = fmaf(w, v.y, accy);
    }

    float inv = 1.0f / den;
    h0 = accx * inv;
    h1 = accy * inv;
}

// ============ aggregate layer1 + bias + relu -> g_hl (fp32) ============
__global__ void __launch_bounds__(256) agg1_kernel(const __half* __restrict__ h,
                                                   const float* __restrict__ b1,
                                                   float* __restrict__ HL) {
    int n = (blockIdx.x * blockDim.x + threadIdx.x) >> 5;
    int lane = threadIdx.x & 31;
    if (n >= NN) return;
    int c0 = 2 * lane;

    float h0, h1;
    gather_node(h, g_as, g_ad, n, lane, h0, h1);
    h0 += b1[c0]; h1 += b1[c0 + 1];
    h0 = (h0 > 0.0f) ? h0 : 0.0f;
    h1 = (h1 > 0.0f) ? h1 : 0.0f;
    *(float2*)(HL + (size_t)n * HID + c0) = make_float2(h0, h1);
}

// ============ final: aggregate layer2 + bias + relu + both heads ============
__global__ void __launch_bounds__(256) agg2_heads_kernel(const __half* __restrict__ h,
                                                         const float* __restrict__ b2,
                                                         const float* __restrict__ Wf,
                                                         const float* __restrict__ bf,
                                                         const float* __restrict__ Ws,
                                                         const float* __restrict__ bs,
                                                         float* __restrict__ out) {
    int n = (blockIdx.x * blockDim.x + threadIdx.x) >> 5;
    int lane = threadIdx.x & 31;
    if (n >= NN) return;
    int c0 = 2 * lane;

    float h0, h1;
    gather_node(h, g_as2, g_ad2, n, lane, h0, h1);
    h0 += b2[c0]; h1 += b2[c0 + 1];
    h0 = (h0 > 0.0f) ? h0 : 0.0f;
    h1 = (h1 > 0.0f) ? h1 : 0.0f;

    float acc[10];
    #pragma unroll
    for (int j = 0; j < 3; j++)
        acc[j] = h0 * Wf[c0 * 3 + j] + h1 * Wf[(c0 + 1) * 3 + j];
    #pragma unroll
    for (int j = 0; j < 7; j++)
        acc[3 + j] = h0 * Ws[c0 * 7 + j] + h1 * Ws[(c0 + 1) * 7 + j];
    #pragma unroll
    for (int j = 0; j < 10; j++) {
        #pragma unroll
        for (int o = 16; o; o >>= 1)
            acc[j] += __shfl_down_sync(0xffffffffu, acc[j], o);
    }
    if (lane == 0) {
        #pragma unroll
        for (int j = 0; j < 3; j++) out[(size_t)n * 3 + j] = acc[j] + bf[j];
        #pragma unroll
        for (int j = 0; j < 7; j++)
            out[(size_t)NN * 3 + (size_t)n * 7 + j] = acc[3 + j] + bs[j];
    }
}

extern "C" void kernel_launch(void* const* d_in, const int* in_sizes, int n_in,
                              void* d_out, int out_size) {
    const float* x    = (const float*)d_in[0];
    const int*   ei   = (const int*)d_in[1];
    const float* W1   = (const float*)d_in[2];
    const float* as1  = (const float*)d_in[3];
    const float* ad1  = (const float*)d_in[4];
    const float* b1   = (const float*)d_in[5];
    const float* W2   = (const float*)d_in[6];
    const float* as2  = (const float*)d_in[7];
    const float* ad2  = (const float*)d_in[8];
    const float* b2   = (const float*)d_in[9];
    const float* Wf   = (const float*)d_in[10];
    const float* bf   = (const float*)d_in[11];
    const float* Ws   = (const float*)d_in[12];
    const float* bs   = (const float*)d_in[13];
    float* out = (float*)d_out;

    __half* d_gh;   cudaGetSymbolAddress((void**)&d_gh,   g_h);
    float*  d_ghl;  cudaGetSymbolAddress((void**)&d_ghl,  g_hl);
    __half* d_gh2;  cudaGetSymbolAddress((void**)&d_gh2,  g_h2);
    float*  d_gas;  cudaGetSymbolAddress((void**)&d_gas,  g_as);
    float*  d_gad;  cudaGetSymbolAddress((void**)&d_gad,  g_ad);
    float*  d_gas2; cudaGetSymbolAddress((void**)&d_gas2, g_as2);
    float*  d_gad2; cudaGetSymbolAddress((void**)&d_gad2, g_ad2);

    const int TB = 256;
    dim3 gNode((NN + TB - 1) / TB);
    dim3 gEdge((NE + TB - 1) / TB);
    dim3 gGemm((NN + 127) / 128);
    dim3 gWarpNode(((size_t)NN * 32 + TB - 1) / TB);

    // ---- adjacency build ----
    zero_kernel<<<gNode, TB>>>();                                  // launch 0
    fill_kernel<<<gEdge, TB>>>(ei);                                // launch 1

    // ---- layer 1 ----
    gemm_kernel<256><<<gGemm, TB>>>(x, W1, as1, ad1, d_gh, d_gas, d_gad);  // launch 2
    agg1_kernel<<<gWarpNode, TB>>>(d_gh, b1, d_ghl);               // launch 3 (profiled)

    // ---- layer 2 ----
    gemm_kernel<64><<<gGemm, TB>>>(d_ghl, W2, as2, ad2, d_gh2, d_gas2, d_gad2);
    agg2_heads_kernel<<<gWarpNode, TB>>>(d_gh2, b2, Wf, bf, Ws, bs, out);
}

// round 13
// speedup vs baseline: 1.2895x; 1.1079x over previous
#include <cuda_runtime.h>
#include <cuda_fp16.h>

#define NN 100000
#define NE 1600000
#define HID 64
#define NEG_SLOPE 0.2f
#define CAP 64              // slots per node incl. self; deg~1+Poisson(16)

// ---------------- scratch (device globals) ----------------
__device__ __half g_h[NN * HID];    // layer-1 pre-attention features (fp16, gather-only)
__device__ float  g_hl[NN * HID];   // layer-1 output (GEMM2 input, fp32)
__device__ __half g_h2[NN * HID];   // layer-2 pre-attention features (fp16)
__device__ float  g_as[NN];
__device__ float  g_ad[NN];
__device__ float  g_as2[NN];
__device__ float  g_ad2[NN];
__device__ int    g_cnt[NN];
__device__ int    g_slots[(size_t)NN * CAP];

// ---------------- f32x2 helpers ----------------
__device__ __forceinline__ unsigned long long ffma2(unsigned long long a,
                                                    unsigned long long b,
                                                    unsigned long long c) {
    unsigned long long d;
    asm("fma.rn.f32x2 %0,%1,%2,%3;" : "=l"(d) : "l"(a), "l"(b), "l"(c));
    return d;
}
__device__ __forceinline__ unsigned long long dup2(float x) {
    unsigned long long r;
    asm("mov.b64 %0,{%1,%1};" : "=l"(r) : "f"(x));
    return r;
}
__device__ __forceinline__ float2 unpk(unsigned long long p) {
    float2 r;
    asm("mov.b64 {%0,%1},%2;" : "=f"(r.x), "=f"(r.y) : "l"(p));
    return r;
}

// ================= adjacency build (slot-based; self-loop pre-seeded) =================
__global__ void zero_kernel() {
    int i = blockIdx.x * blockDim.x + threadIdx.x;
    if (i < NN) {
        g_cnt[i] = 1;                       // slot 0 = self loop
        g_slots[(size_t)i * CAP] = i;
    }
}
__global__ void fill_kernel(const int* __restrict__ ei) {
    int e = blockIdx.x * blockDim.x + threadIdx.x;
    if (e >= NE) return;
    int s = ei[e], d = ei[NE + e];
    int idx = atomicAdd(&g_cnt[d], 1);
    if (idx < CAP) g_slots[(size_t)d * CAP + idx] = s;
}

// ============ tiled GEMM (128x64, FFMA2) + fused scores; fp16 H output ============
template<int K>
__global__ void __launch_bounds__(256) gemm_kernel(const float* __restrict__ X,
                                                   const float* __restrict__ W,
                                                   const float* __restrict__ a_s,
                                                   const float* __restrict__ a_d,
                                                   __half* __restrict__ H,
                                                   float* __restrict__ as_out,
                                                   float* __restrict__ ad_out) {
    __shared__ float xs[16][132];
    __shared__ float ws[16][64];
    int t = threadIdx.x;
    int rowblk = blockIdx.x * 128;

    int col4 = (t & 15) * 4;
    int r0   = (t >> 4) * 8;

    unsigned long long acc[4][4];
    #pragma unroll
    for (int i = 0; i < 4; i++)
        #pragma unroll
        for (int j = 0; j < 4; j++) acc[i][j] = 0ull;

    int lrow = t >> 1;
    int lk   = (t & 1) * 8;
    int grow = rowblk + lrow; if (grow >= NN) grow = NN - 1;
    const float4* xsrc = (const float4*)(X + (size_t)grow * K);

    for (int k0 = 0; k0 < K; k0 += 16) {
        float4 v0 = xsrc[(k0 + lk) >> 2];
        float4 v1 = xsrc[(k0 + lk + 4) >> 2];
        float4 wv4 = ((const float4*)(W + k0 * 64))[t];
        __syncthreads();
        xs[lk + 0][lrow] = v0.x; xs[lk + 1][lrow] = v0.y;
        xs[lk + 2][lrow] = v0.z; xs[lk + 3][lrow] = v0.w;
        xs[lk + 4][lrow] = v1.x; xs[lk + 5][lrow] = v1.y;
        xs[lk + 6][lrow] = v1.z; xs[lk + 7][lrow] = v1.w;
        ((float4*)ws)[t] = wv4;
        __syncthreads();
        #pragma unroll
        for (int kk = 0; kk < 16; kk++) {
            float4 wv = *(const float4*)&ws[kk][col4];
            unsigned long long wd0 = dup2(wv.x), wd1 = dup2(wv.y),
                               wd2 = dup2(wv.z), wd3 = dup2(wv.w);
            #pragma unroll
            for (int i = 0; i < 4; i++) {
                unsigned long long xp =
                    *(const unsigned long long*)&xs[kk][r0 + 2 * i];
                acc[i][0] = ffma2(xp, wd0, acc[i][0]);
                acc[i][1] = ffma2(xp, wd1, acc[i][1]);
                acc[i][2] = ffma2(xp, wd2, acc[i][2]);
                acc[i][3] = ffma2(xp, wd3, acc[i][3]);
            }
        }
    }

    int orow = rowblk + r0;
    float2 c[4][4];
    #pragma unroll
    for (int i = 0; i < 4; i++) {
        #pragma unroll
        for (int j = 0; j < 4; j++) c[i][j] = unpk(acc[i][j]);
        int rlo = orow + 2 * i, rhi = rlo + 1;
        if (rlo < NN) {
            union { __half2 h[2]; uint2 u; } pk;
            pk.h[0] = __floats2half2_rn(c[i][0].x, c[i][1].x);
            pk.h[1] = __floats2half2_rn(c[i][2].x, c[i][3].x);
            *(uint2*)(H + (size_t)rlo * 64 + col4) = pk.u;
        }
        if (rhi < NN) {
            union { __half2 h[2]; uint2 u; } pk;
            pk.h[0] = __floats2half2_rn(c[i][0].y, c[i][1].y);
            pk.h[1] = __floats2half2_rn(c[i][2].y, c[i][3].y);
            *(uint2*)(H + (size_t)rhi * 64 + col4) = pk.u;
        }
    }

    float4 asv = *(const float4*)(a_s + col4);
    float4 adv = *(const float4*)(a_d + col4);
    float ps[8], pd[8];
    #pragma unroll
    for (int i = 0; i < 4; i++) {
        ps[2*i]   = c[i][0].x*asv.x + c[i][1].x*asv.y + c[i][2].x*asv.z + c[i][3].x*asv.w;
        ps[2*i+1] = c[i][0].y*asv.x + c[i][1].y*asv.y + c[i][2].y*asv.z + c[i][3].y*asv.w;
        pd[2*i]   = c[i][0].x*adv.x + c[i][1].x*adv.y + c[i][2].x*adv.z + c[i][3].x*adv.w;
        pd[2*i+1] = c[i][0].y*adv.x + c[i][1].y*adv.y + c[i][2].y*adv.z + c[i][3].y*adv.w;
    }
    #pragma unroll
    for (int r = 0; r < 8; r++) {
        #pragma unroll
        for (int o = 8; o; o >>= 1) {
            ps[r] += __shfl_down_sync(0xffffffffu, ps[r], o, 16);
            pd[r] += __shfl_down_sync(0xffffffffu, pd[r], o, 16);
        }
    }
    if ((t & 15) == 0) {
        #pragma unroll
        for (int r = 0; r < 8; r++) {
            int row = orow + r;
            if (row < NN) { as_out[row] = ps[r]; ad_out[row] = pd[r]; }
        }
    }
}

// -------- cooperative softmax-weighted gather (R9 layout; self in slot 0) --------
__device__ __forceinline__ void gather_node(const __half* __restrict__ h,
                                            const float* __restrict__ as,
                                            const float* __restrict__ ad,
                                            int n, int lane,
                                            float& h0, float& h1) {
    int deg = g_cnt[n];
    if (deg > CAP) deg = CAP;
    const int* slots = g_slots + (size_t)n * CAP;
    int c0 = 2 * lane;
    float adn = ad[n];

    int   sA = 0, sB = 0;
    float wA = 0.0f, wB = 0.0f;
    if (lane < deg) {
        sA = slots[lane];
        float e = as[sA] + adn;
        wA = __expf((e > 0.0f) ? e : NEG_SLOPE * e);
    }
    if (lane + 32 < deg) {
        sB = slots[lane + 32];
        float e = as[sB] + adn;
        wB = __expf((e > 0.0f) ? e : NEG_SLOPE * e);
    }

    float den = wA + wB;
    #pragma unroll
    for (int o = 16; o; o >>= 1)
        den += __shfl_xor_sync(0xffffffffu, den, o);

    float accx = 0.0f, accy = 0.0f;

    int m1 = (deg < 32) ? deg : 32;
    int j = 0;
    for (; j + 4 <= m1; j += 4) {
        int t0 = __shfl_sync(0xffffffffu, sA, j);
        int t1 = __shfl_sync(0xffffffffu, sA, j + 1);
        int t2 = __shfl_sync(0xffffffffu, sA, j + 2);
        int t3 = __shfl_sync(0xffffffffu, sA, j + 3);
        float2 v0 = __half22float2(*(const __half2*)(h + (size_t)t0 * HID + c0));
        float2 v1 = __half22float2(*(const __half2*)(h + (size_t)t1 * HID + c0));
        float2 v2 = __half22float2(*(const __half2*)(h + (size_t)t2 * HID + c0));
        float2 v3 = __half22float2(*(const __half2*)(h + (size_t)t3 * HID + c0));
        float w0 = __shfl_sync(0xffffffffu, wA, j);
        float w1 = __shfl_sync(0xffffffffu, wA, j + 1);
        float w2 = __shfl_sync(0xffffffffu, wA, j + 2);
        float w3 = __shfl_sync(0xffffffffu, wA, j + 3);
        accx = fmaf(w0, v0.x, accx); accy = fmaf(w0, v0.y, accy);
        accx = fmaf(w1, v1.x, accx); accy = fmaf(w1, v1.y, accy);
        accx = fmaf(w2, v2.x, accx); accy = fmaf(w2, v2.y, accy);
        accx = fmaf(w3, v3.x, accx); accy = fmaf(w3, v3.y, accy);
    }
    for (; j < m1; j++) {
        int   s = __shfl_sync(0xffffffffu, sA, j);
        float w = __shfl_sync(0xffffffffu, wA, j);
        float2 v = __half22float2(*(const __half2*)(h + (size_t)s * HID + c0));
        accx = fmaf(w, v.x, accx); accy = fmaf(w, v.y, accy);
    }
    int m2 = deg - 32;
    j = 0;
    for (; j + 4 <= m2; j += 4) {
        int t0 = __shfl_sync(0xffffffffu, sB, j);
        int t1 = __shfl_sync(0xffffffffu, sB, j + 1);
        int t2 = __shfl_sync(0xffffffffu, sB, j + 2);
        int t3 = __shfl_sync(0xffffffffu, sB, j + 3);
        float2 v0 = __half22float2(*(const __half2*)(h + (size_t)t0 * HID + c0));
        float2 v1 = __half22float2(*(const __half2*)(h + (size_t)t1 * HID + c0));
        float2 v2 = __half22float2(*(const __half2*)(h + (size_t)t2 * HID + c0));
        float2 v3 = __half22float2(*(const __half2*)(h + (size_t)t3 * HID + c0));
        float w0 = __shfl_sync(0xffffffffu, wB, j);
        float w1 = __shfl_sync(0xffffffffu, wB, j + 1);
        float w2 = __shfl_sync(0xffffffffu, wB, j + 2);
        float w3 = __shfl_sync(0xffffffffu, wB, j + 3);
        accx = fmaf(w0, v0.x, accx); accy = fmaf(w0, v0.y, accy);
        accx = fmaf(w1, v1.x, accx); accy = fmaf(w1, v1.y, accy);
        accx = fmaf(w2, v2.x, accx); accy = fmaf(w2, v2.y, accy);
        accx = fmaf(w3, v3.x, accx); accy = fmaf(w3, v3.y, accy);
    }
    for (; j < m2; j++) {
        int   s = __shfl_sync(0xffffffffu, sB, j);
        float w = __shfl_sync(0xffffffffu, wB, j);
        float2 v = __half22float2(*(const __half2*)(h + (size_t)s * HID + c0));
        accx = fmaf(w, v.x, accx); accy = fmaf(w, v.y, accy);
    }

    float inv = 1.0f / den;
    h0 = accx * inv;
    h1 = accy * inv;
}

// ============ aggregate layer1 + bias + relu -> g_hl (fp32) ============
__global__ void __launch_bounds__(256) agg1_kernel(const __half* __restrict__ h,
                                                   const float* __restrict__ b1,
                                                   float* __restrict__ HL) {
    int n = (blockIdx.x * blockDim.x + threadIdx.x) >> 5;
    int lane = threadIdx.x & 31;
    if (n >= NN) return;
    int c0 = 2 * lane;

    float h0, h1;
    gather_node(h, g_as, g_ad, n, lane, h0, h1);
    h0 += b1[c0]; h1 += b1[c0 + 1];
    h0 = (h0 > 0.0f) ? h0 : 0.0f;
    h1 = (h1 > 0.0f) ? h1 : 0.0f;
    *(float2*)(HL + (size_t)n * HID + c0) = make_float2(h0, h1);
}

// ============ final: aggregate layer2 + bias + relu + both heads ============
__global__ void __launch_bounds__(256) agg2_heads_kernel(const __half* __restrict__ h,
                                                         const float* __restrict__ b2,
                                                         const float* __restrict__ Wf,
                                                         const float* __restrict__ bf,
                                                         const float* __restrict__ Ws,
                                                         const float* __restrict__ bs,
                                                         float* __restrict__ out) {
    int n = (blockIdx.x * blockDim.x + threadIdx.x) >> 5;
    int lane = threadIdx.x & 31;
    if (n >= NN) return;
    int c0 = 2 * lane;

    float h0, h1;
    gather_node(h, g_as2, g_ad2, n, lane, h0, h1);
    h0 += b2[c0]; h1 += b2[c0 + 1];
    h0 = (h0 > 0.0f) ? h0 : 0.0f;
    h1 = (h1 > 0.0f) ? h1 : 0.0f;

    float acc[10];
    #pragma unroll
    for (int j = 0; j < 3; j++)
        acc[j] = h0 * Wf[c0 * 3 + j] + h1 * Wf[(c0 + 1) * 3 + j];
    #pragma unroll
    for (int j = 0; j < 7; j++)
        acc[3 + j] = h0 * Ws[c0 * 7 + j] + h1 * Ws[(c0 + 1) * 7 + j];
    #pragma unroll
    for (int j = 0; j < 10; j++) {
        #pragma unroll
        for (int o = 16; o; o >>= 1)
            acc[j] += __shfl_down_sync(0xffffffffu, acc[j], o);
    }
    if (lane == 0) {
        #pragma unroll
        for (int j = 0; j < 3; j++) out[(size_t)n * 3 + j] = acc[j] + bf[j];
        #pragma unroll
        for (int j = 0; j < 7; j++)
            out[(size_t)NN * 3 + (size_t)n * 7 + j] = acc[3 + j] + bs[j];
    }
}

extern "C" void kernel_launch(void* const* d_in, const int* in_sizes, int n_in,
                              void* d_out, int out_size) {
    const float* x    = (const float*)d_in[0];
    const int*   ei   = (const int*)d_in[1];
    const float* W1   = (const float*)d_in[2];
    const float* as1  = (const float*)d_in[3];
    const float* ad1  = (const float*)d_in[4];
    const float* b1   = (const float*)d_in[5];
    const float* W2   = (const float*)d_in[6];
    const float* as2  = (const float*)d_in[7];
    const float* ad2  = (const float*)d_in[8];
    const float* b2   = (const float*)d_in[9];
    const float* Wf   = (const float*)d_in[10];
    const float* bf   = (const float*)d_in[11];
    const float* Ws   = (const float*)d_in[12];
    const float* bs   = (const float*)d_in[13];
    float* out = (float*)d_out;

    __half* d_gh;   cudaGetSymbolAddress((void**)&d_gh,   g_h);
    float*  d_ghl;  cudaGetSymbolAddress((void**)&d_ghl,  g_hl);
    __half* d_gh2;  cudaGetSymbolAddress((void**)&d_gh2,  g_h2);
    float*  d_gas;  cudaGetSymbolAddress((void**)&d_gas,  g_as);
    float*  d_gad;  cudaGetSymbolAddress((void**)&d_gad,  g_ad);
    float*  d_gas2; cudaGetSymbolAddress((void**)&d_gas2, g_as2);
    float*  d_gad2; cudaGetSymbolAddress((void**)&d_gad2, g_ad2);

    const int TB = 256;
    dim3 gNode((NN + TB - 1) / TB);
    dim3 gEdge((NE + TB - 1) / TB);
    dim3 gGemm((NN + 127) / 128);
    dim3 gWarpNode(((size_t)NN * 32 + TB - 1) / TB);

    // Fork a side stream off the capture stream so the adjacency build
    // (g_cnt/g_slots) overlaps gemm1 (g_h/g_as/g_ad) — disjoint data.
    // Streams/events are host objects (no device allocation); they are not
    // destroyed here because the enclosing stream capture is still active.
    cudaStream_t s2;
    cudaEvent_t evFork, evJoin;
    cudaStreamCreateWithFlags(&s2, cudaStreamNonBlocking);
    cudaEventCreateWithFlags(&evFork, cudaEventDisableTiming);
    cudaEventCreateWithFlags(&evJoin, cudaEventDisableTiming);

    cudaEventRecord(evFork, 0);
    cudaStreamWaitEvent(s2, evFork, 0);

    // ---- adjacency build on side stream ----
    zero_kernel<<<gNode, TB, 0, s2>>>();                           // launch 0
    fill_kernel<<<gEdge, TB, 0, s2>>>(ei);                         // launch 1

    // ---- layer-1 GEMM + scores on main stream (overlapped) ----
    gemm_kernel<256><<<gGemm, TB>>>(x, W1, as1, ad1, d_gh, d_gas, d_gad);  // launch 2

    cudaEventRecord(evJoin, s2);
    cudaStreamWaitEvent(0, evJoin, 0);

    // ---- rest of the pipeline (needs both) ----
    agg1_kernel<<<gWarpNode, TB>>>(d_gh, b1, d_ghl);               // launch 3 (profiled)
    gemm_kernel<64><<<gGemm, TB>>>(d_ghl, W2, as2, ad2, d_gh2, d_gas2, d_gad2);
    agg2_heads_kernel<<<gWarpNode, TB>>>(d_gh2, b2, Wf, bf, Ws, bs, out);
}